// round 16
// baseline (speedup 1.0000x reference)
#include <cuda_runtime.h>
#include <cuda_fp16.h>
#include <cstdint>

#define BB 24
#define DM 128
#define HH 8
#define DK 16
#define LL 512
#define HB (HH*BB)   // 192

__device__ __half gXh[BB*DM*LL], gXl[BB*DM*LL];
__device__ __half gQh[HB*DK*LL], gQl[HB*DK*LL];
__device__ __half gKh[HB*DK*LL], gKl[HB*DK*LL];
__device__ __half gVh[HB*DK*LL];
__device__ __half gHh[BB*DM*LL], gHl[BB*DM*LL];
__device__ int c_prep[BB],  c_prepdone[BB];
__device__ int c_qkv[HB],   c_qkvdone[HB];
__device__ int c_attn[BB],  c_attndone[BB];

__device__ __forceinline__ uint32_t smem_u32(const void* p) {
    uint32_t a;
    asm("{ .reg .u64 t; cvta.to.shared.u64 t, %1; cvt.u32.u64 %0, t; }" : "=r"(a) : "l"(p));
    return a;
}
__device__ __forceinline__ void ldsm4(uint32_t* r, uint32_t a) {
    asm volatile("ldmatrix.sync.aligned.m8n8.x4.shared.b16 {%0,%1,%2,%3}, [%4];"
        : "=r"(r[0]), "=r"(r[1]), "=r"(r[2]), "=r"(r[3]) : "r"(a));
}
__device__ __forceinline__ void ldsm4t(uint32_t* r, uint32_t a) {
    asm volatile("ldmatrix.sync.aligned.m8n8.x4.trans.shared.b16 {%0,%1,%2,%3}, [%4];"
        : "=r"(r[0]), "=r"(r[1]), "=r"(r[2]), "=r"(r[3]) : "r"(a));
}
__device__ __forceinline__ void mma_f16(float* d, const uint32_t* a, const uint32_t* b) {
    asm volatile("mma.sync.aligned.m16n8k16.row.col.f32.f16.f16.f32 "
        "{%0,%1,%2,%3}, {%4,%5,%6,%7}, {%8,%9}, {%0,%1,%2,%3};"
        : "+f"(d[0]), "+f"(d[1]), "+f"(d[2]), "+f"(d[3])
        : "r"(a[0]), "r"(a[1]), "r"(a[2]), "r"(a[3]), "r"(b[0]), "r"(b[1]));
}
__device__ __forceinline__ float ex2f(float x) {
    float r; asm("ex2.approx.f32 %0, %1;" : "=f"(r) : "f"(x)); return r;
}
__device__ __forceinline__ uint32_t cvt_f16x2(float hi, float lo) {
    uint32_t r; asm("cvt.rn.f16x2.f32 %0, %1, %2;" : "=r"(r) : "f"(hi), "f"(lo)); return r;
}
__device__ __forceinline__ uint32_t ex2_f16x2(uint32_t x) {
    uint32_t r; asm("ex2.approx.f16x2 %0, %1;" : "=r"(r) : "r"(x)); return r;
}
__device__ __forceinline__ void packhl(float p0, float p1, uint32_t& h, uint32_t& l) {
    __half2 hh = __floats2half2_rn(p0, p1);
    float2 f = __half22float2(hh);
    __half2 ll = __floats2half2_rn(p0 - f.x, p1 - f.y);
    h = *(uint32_t*)&hh; l = *(uint32_t*)&ll;
}
__device__ __forceinline__ uint32_t packh(float p0, float p1) {
    __half2 hh = __floats2half2_rn(p0, p1);
    return *(uint32_t*)&hh;
}
__device__ __forceinline__ void split1(float v, __half& h, __half& l) {
    h = __float2half_rn(v);
    l = __float2half_rn(v - __half2float(h));
}
__device__ __forceinline__ void spin_until(volatile int* c, int target) {
    while (*c < target) __nanosleep(64);
}
__device__ __forceinline__ void consume(int* cnt, int target, int* done, int ncons) {
    spin_until(cnt, target);
    __threadfence();
    int old = atomicAdd(done, 1);
    if (old == ncons - 1) { *cnt = 0; *done = 0; }
}

// qkv role smem:
#define QW_H 0          // 48*136*2 = 13056
#define QW_L 13056
#define QX_H 26112      // 128*144  = 18432
#define QX_L 44544      // end 62976
// attn role smem:
#define A_QH 0
#define A_QL 16640
#define A_VH 33280
#define A_KH 49920
#define A_KL 54272
// out role smem:
#define OW_H 0
#define OW_L 8704
#define OX_H 17408
#define OX_L 35840
#define SMEM_ALL 62976

#define NPREP 96
#define NQKV  1536     // 192 hb x 8 l-eighths (64 l each)
#define NATTN 768
#define NOUT  768

__global__ void __launch_bounds__(256, 3) k_all(const float* __restrict__ x,
                                                const float* __restrict__ Wq,
                                                const float* __restrict__ Wk,
                                                const float* __restrict__ Wv,
                                                const float* __restrict__ Wo,
                                                float* __restrict__ out)
{
    extern __shared__ char smc[];
    const uint32_t su = smem_u32(smc);
    const int bid = blockIdx.x, t = threadIdx.x;
    const int w = t >> 5, ln = t & 31;
    const int rsel = ln & 15;
    const uint32_t csel = (uint32_t)(ln >> 4) * 16;
    const int trow = (ln & 7) + ((ln >> 4) << 3);
    const uint32_t tcb = (uint32_t)((ln >> 3) & 1) * 16;

    if (bid < NPREP) {
        // ================= prep: x -> fp16 hi/lo =================
        const int b = bid >> 2;
        const size_t base = (size_t)bid * 4096;           // float4 units
        #pragma unroll
        for (int j = 0; j < 16; ++j) {
            size_t i = base + t + (size_t)j * 256;
            float4 v = *(const float4*)(x + i * 4);
            uint32_t h0,l0,h1,l1;
            packhl(v.x, v.y, h0, l0); packhl(v.z, v.w, h1, l1);
            uint2 uh; uh.x = h0; uh.y = h1;
            uint2 ul; ul.x = l0; ul.y = l1;
            *(uint2*)&gXh[i * 4] = uh;
            *(uint2*)&gXl[i * 4] = ul;
        }
        __threadfence();
        __syncthreads();
        if (t == 0) atomicAdd(&c_prep[b], 1);
        return;
    }

    if (bid < NPREP + NQKV) {
        // ================= qkv: (hb, l-eighth of 64) =================
        const int qb = bid - NPREP;
        const int hb = qb >> 3, lq = qb & 7;
        const int b = hb % BB;
        const int lw = w & 3, mg = w >> 2;   // 4 l-groups x 2 mt-groups
        const int nmt = (mg == 0) ? 2 : 1;

        __half* sWh = (__half*)(smc + QW_H);
        __half* sWl = (__half*)(smc + QW_L);

        for (int i4 = t; i4 < 1536; i4 += 256) {
            int r = i4 >> 5, c4 = i4 & 31;
            const float* src = (r < 16) ? (Wq + (size_t)hb*2048 + r*128)
                             : (r < 32) ? (Wk + (size_t)hb*2048 + (r-16)*128)
                                        : (Wv + (size_t)hb*2048 + (r-32)*128);
            float4 v = *(const float4*)(src + c4*4);
            uint32_t h0,l0,h1,l1;
            packhl(v.x, v.y, h0, l0); packhl(v.z, v.w, h1, l1);
            uint2 uh; uh.x = h0; uh.y = h1;
            uint2 ul; ul.x = l0; ul.y = l1;
            *(uint2*)&sWh[r*136 + c4*4] = uh;
            *(uint2*)&sWl[r*136 + c4*4] = ul;
        }

        if (t == 0) consume(&c_prep[b], 4, &c_prepdone[b], 64);
        __syncthreads();

        // stage x chunk: 128 d x 64 l, pitch 144 B
        for (int i4 = t; i4 < 1024; i4 += 256) {
            int d = i4 >> 3, j = i4 & 7;
            uint32_t dofs = (uint32_t)(d*144 + j*16);
            size_t gofs = (size_t)b*65536 + (size_t)d*512 + lq*64 + j*8;
            *(uint4*)(smc + QX_H + dofs) = *(const uint4*)(gXh + gofs);
            *(uint4*)(smc + QX_L + dofs) = *(const uint4*)(gXl + gofs);
        }
        __syncthreads();

        float acc[2][2][4];
        #pragma unroll
        for (int mt = 0; mt < 2; ++mt)
            #pragma unroll
            for (int nt = 0; nt < 2; ++nt)
                #pragma unroll
                for (int r = 0; r < 4; ++r) acc[mt][nt][r] = 0.f;

        #pragma unroll
        for (int kt = 0; kt < 8; ++kt) {
            uint32_t bh[2][2], bl[2][2], r4[4];
            uint32_t ad = su + QX_H + (uint32_t)((kt*16 + trow)*144) + (uint32_t)(lw*16)*2 + tcb;
            ldsm4t(r4, ad);
            bh[0][0]=r4[0]; bh[0][1]=r4[2]; bh[1][0]=r4[1]; bh[1][1]=r4[3];
            ldsm4t(r4, ad + (QX_L - QX_H));
            bl[0][0]=r4[0]; bl[0][1]=r4[2]; bl[1][0]=r4[1]; bl[1][1]=r4[3];
            #pragma unroll
            for (int mt = 0; mt < 2; ++mt) {
                if (mt >= nmt) break;
                int wrow = (mg ? 2 : mt) * 16 + rsel;
                uint32_t ah[4], al[4];
                uint32_t aad = su + QW_H + (uint32_t)(wrow*272) + csel + kt*32;
                ldsm4(ah, aad);
                ldsm4(al, aad + (QW_L - QW_H));
                #pragma unroll
                for (int nt = 0; nt < 2; ++nt) {
                    mma_f16(acc[mt][nt], ah, bh[nt]);
                    mma_f16(acc[mt][nt], ah, bl[nt]);
                    mma_f16(acc[mt][nt], al, bh[nt]);
                }
            }
        }

        #pragma unroll
        for (int mt = 0; mt < 2; ++mt) {
            if (mt >= nmt) break;
            #pragma unroll
            for (int nt = 0; nt < 2; ++nt) {
                int rr = ln >> 2;
                int cc = lq*64 + lw*16 + nt*8 + (ln & 3)*2;
                size_t o0 = (size_t)hb*8192 + (size_t)rr*512 + cc;
                size_t o1 = (size_t)hb*8192 + (size_t)(rr+8)*512 + cc;
                if (mg) {
                    *(uint32_t*)&gVh[o0] = packh(acc[mt][nt][0], acc[mt][nt][1]);
                    *(uint32_t*)&gVh[o1] = packh(acc[mt][nt][2], acc[mt][nt][3]);
                } else {
                    __half* dh = mt ? gKh : gQh;
                    __half* dl = mt ? gKl : gQl;
                    uint32_t h0,l0,h1,l1;
                    packhl(acc[mt][nt][0], acc[mt][nt][1], h0, l0);
                    packhl(acc[mt][nt][2], acc[mt][nt][3], h1, l1);
                    *(uint32_t*)&dh[o0] = h0; *(uint32_t*)&dl[o0] = l0;
                    *(uint32_t*)&dh[o1] = h1; *(uint32_t*)&dl[o1] = l1;
                }
            }
        }
        __threadfence();
        __syncthreads();
        if (t == 0) atomicAdd(&c_qkv[hb], 1);
        return;
    }

    if (bid < NPREP + NQKV + NATTN) {
        // ================= attention =================
        const int ab = bid - NPREP - NQKV;
        const int hb = ab >> 2, ms = ab & 3;
        const int b = hb % BB, h = hb / BB;
        const int m0 = ms * 128;

        if (t == 0) consume(&c_qkv[hb], 8, &c_qkvdone[hb], 4);
        __syncthreads();

        {
            const __half* s0 = gQh + (size_t)hb*8192;
            const __half* s1 = gQl + (size_t)hb*8192;
            const __half* s2 = gVh + (size_t)hb*8192;
            for (int j = t; j < 1024; j += 256) {
                int k = j >> 6, c = j & 63;
                uint32_t dofs = (uint32_t)(k*1040 + c*16);
                *(uint4*)(smc + A_QH + dofs) = *(const uint4*)(s0 + k*512 + c*8);
                *(uint4*)(smc + A_QL + dofs) = *(const uint4*)(s1 + k*512 + c*8);
                *(uint4*)(smc + A_VH + dofs) = *(const uint4*)(s2 + k*512 + c*8);
            }
            for (int j = t; j < 256; j += 256) {
                int k = j >> 4, c = j & 15;
                uint32_t dofs = (uint32_t)(k*272 + c*16);
                *(uint4*)(smc + A_KH + dofs) = *(const uint4*)(gKh + (size_t)hb*8192 + k*512 + m0 + c*8);
                *(uint4*)(smc + A_KL + dofs) = *(const uint4*)(gKl + (size_t)hb*8192 + k*512 + m0 + c*8);
            }
        }
        __syncthreads();

        uint32_t kh[4], kl[4];
        {
            uint32_t ad = su + A_KH + (uint32_t)(trow*272) + (uint32_t)(w*16)*2 + tcb;
            ldsm4t(kh, ad);
            ldsm4t(kl, ad + (A_KL - A_KH));
        }

        uint32_t bones[2];
        bones[0] = (ln < 4) ? 0x3C003C00u : 0u;
        bones[1] = bones[0];

        float mx[2] = {-1e30f, -1e30f}, O[2][4], Od[4];
        #pragma unroll
        for (int vt = 0; vt < 2; ++vt)
            #pragma unroll
            for (int r = 0; r < 4; ++r) O[vt][r] = 0.f;
        #pragma unroll
        for (int r = 0; r < 4; ++r) Od[r] = 0.f;

        const float C = 0.36067376022224085f;

        for (int c = 0; c < 16; ++c) {
            uint32_t vb[2][2][2];
            #pragma unroll
            for (int st = 0; st < 2; ++st) {
                uint32_t r4[4];
                uint32_t ad = su + A_VH + (uint32_t)(rsel * 1040 + (c*32 + st*16) * 2) + csel;
                ldsm4(r4, ad);
                vb[st][0][0]=r4[0]; vb[st][0][1]=r4[2]; vb[st][1][0]=r4[1]; vb[st][1][1]=r4[3];
            }
            uint32_t qh[4][2], ql[4][2];
            #pragma unroll
            for (int q = 0; q < 2; ++q) {
                uint32_t r4[4];
                uint32_t ad = su + A_QH + (uint32_t)(trow*1040) + (uint32_t)((c*32 + q*16)*2) + tcb;
                ldsm4t(r4, ad);
                qh[2*q][0]=r4[0]; qh[2*q][1]=r4[2]; qh[2*q+1][0]=r4[1]; qh[2*q+1][1]=r4[3];
                ldsm4t(r4, ad + (A_QL - A_QH));
                ql[2*q][0]=r4[0]; ql[2*q][1]=r4[2]; ql[2*q+1][0]=r4[1]; ql[2*q+1][1]=r4[3];
            }

            float s[4][4];
            #pragma unroll
            for (int nt = 0; nt < 4; ++nt) {
                #pragma unroll
                for (int r = 0; r < 4; ++r) s[nt][r] = 0.f;
                mma_f16(s[nt], kh, qh[nt]);
                mma_f16(s[nt], kl, qh[nt]);
                mma_f16(s[nt], kh, ql[nt]);
            }

            float cA = -1e30f, cB = -1e30f;
            #pragma unroll
            for (int nt = 0; nt < 4; ++nt) {
                cA = fmaxf(cA, fmaxf(s[nt][0], s[nt][1]));
                cB = fmaxf(cB, fmaxf(s[nt][2], s[nt][3]));
            }
            cA = fmaxf(cA, __shfl_xor_sync(0xffffffffu, cA, 1));
            cA = fmaxf(cA, __shfl_xor_sync(0xffffffffu, cA, 2));
            cB = fmaxf(cB, __shfl_xor_sync(0xffffffffu, cB, 1));
            cB = fmaxf(cB, __shfl_xor_sync(0xffffffffu, cB, 2));
            float mA = fmaxf(mx[0], cA), mB = fmaxf(mx[1], cB);
            float sA = ex2f((mx[0] - mA) * C), sB = ex2f((mx[1] - mB) * C);
            mx[0] = mA; mx[1] = mB;
            #pragma unroll
            for (int vt = 0; vt < 2; ++vt) {
                O[vt][0] *= sA; O[vt][1] *= sA;
                O[vt][2] *= sB; O[vt][3] *= sB;
            }
            Od[0] *= sA; Od[2] *= sB;

            const float nmA = -mA * C, nmB = -mB * C;
            uint32_t ph[4][2];
            #pragma unroll
            for (int nt = 0; nt < 4; ++nt) {
                float x0 = fmaf(s[nt][0], C, nmA);
                float x1 = fmaf(s[nt][1], C, nmA);
                float x2 = fmaf(s[nt][2], C, nmB);
                float x3 = fmaf(s[nt][3], C, nmB);
                ph[nt][0] = ex2_f16x2(cvt_f16x2(x1, x0));
                ph[nt][1] = ex2_f16x2(cvt_f16x2(x3, x2));
            }

            #pragma unroll
            for (int st = 0; st < 2; ++st) {
                uint32_t ah[4];
                ah[0] = ph[2*st][0];
                ah[1] = ph[2*st][1];
                ah[2] = ph[2*st+1][0];
                ah[3] = ph[2*st+1][1];
                #pragma unroll
                for (int vt = 0; vt < 2; ++vt)
                    mma_f16(O[vt], ah, vb[st][vt]);
                mma_f16(Od, ah, bones);
            }
        }

        float dnA = __shfl_sync(0xffffffffu, Od[0], ln & 28);
        float dnB = __shfl_sync(0xffffffffu, Od[2], ln & 28);
        float inv[2];
        inv[0] = 1.0f / dnA;
        inv[1] = 1.0f / dnB;

        __half* dh = gHh + ((size_t)b * DM + h * DK) * LL;
        __half* dl = gHl + ((size_t)b * DM + h * DK) * LL;
        #pragma unroll
        for (int vt = 0; vt < 2; ++vt)
            #pragma unroll
            for (int r = 0; r < 4; ++r) {
                int m = m0 + w*16 + (ln >> 2) + ((r >> 1) & 1) * 8;
                int v = vt*8 + (ln & 3)*2 + (r & 1);
                float val = O[vt][r] * inv[(r >> 1) & 1];
                __half hi, lo; split1(val, hi, lo);
                dh[(size_t)v * LL + m] = hi;
                dl[(size_t)v * LL + m] = lo;
            }
        __threadfence();
        __syncthreads();
        if (t == 0) atomicAdd(&c_attn[b], 1);
        return;
    }

    // ================= output GEMM =================
    {
        const int obid = bid - NPREP - NQKV - NATTN;
        const int lt = obid & 7, mh = (obid >> 3) & 3, b = obid >> 5;
        __half* sWh = (__half*)(smc + OW_H);
        __half* sWl = (__half*)(smc + OW_L);
        const int lg = w & 3, mg = w >> 2;

        for (int i4 = t; i4 < 1024; i4 += 256) {
            int r = i4 >> 5, c4 = i4 & 31;
            float4 v = *(const float4*)(Wo + (size_t)b*16384 + (size_t)(mh*32 + r)*128 + c4*4);
            uint32_t h0,l0,h1,l1;
            packhl(v.x, v.y, h0, l0); packhl(v.z, v.w, h1, l1);
            uint2 uh; uh.x = h0; uh.y = h1;
            uint2 ul; ul.x = l0; ul.y = l1;
            *(uint2*)&sWh[r*136 + c4*4] = uh;
            *(uint2*)&sWl[r*136 + c4*4] = ul;
        }

        if (t == 0) consume(&c_attn[b], 32, &c_attndone[b], 32);
        __syncthreads();

        for (int i4 = t; i4 < 1024; i4 += 256) {
            int d = i4 >> 3, j = i4 & 7;
            uint32_t dofs = (uint32_t)(d*144 + j*16);
            size_t gofs = (size_t)b*65536 + (size_t)d*512 + lt*64 + j*8;
            *(uint4*)(smc + OX_H + dofs) = *(const uint4*)(gHh + gofs);
            *(uint4*)(smc + OX_L + dofs) = *(const uint4*)(gHl + gofs);
        }
        __syncthreads();

        float acc[2][4];
        #pragma unroll
        for (int nt = 0; nt < 2; ++nt)
            #pragma unroll
            for (int r = 0; r < 4; ++r) acc[nt][r] = 0.f;

        #pragma unroll
        for (int kt = 0; kt < 8; ++kt) {
            uint32_t bh[2][2], bl[2][2], r4[4];
            uint32_t ad = su + OX_H + (uint32_t)((kt*16 + trow)*144) + (uint32_t)(lg*16)*2 + tcb;
            ldsm4t(r4, ad);
            bh[0][0]=r4[0]; bh[0][1]=r4[2]; bh[1][0]=r4[1]; bh[1][1]=r4[3];
            ldsm4t(r4, ad + (OX_L - OX_H));
            bl[0][0]=r4[0]; bl[0][1]=r4[2]; bl[1][0]=r4[1]; bl[1][1]=r4[3];
            uint32_t ah[4], al[4];
            uint32_t aad = su + OW_H + (uint32_t)((mg*16 + rsel)*272) + csel + kt*32;
            ldsm4(ah, aad);
            ldsm4(al, aad + (OW_L - OW_H));
            #pragma unroll
            for (int nt = 0; nt < 2; ++nt) {
                mma_f16(acc[nt], ah, bh[nt]);
                mma_f16(acc[nt], ah, bl[nt]);
                mma_f16(acc[nt], al, bh[nt]);
            }
        }

        #pragma unroll
        for (int nt = 0; nt < 2; ++nt) {
            int rr = mh*32 + mg*16 + (ln >> 2);
            int cc = lt*64 + lg*16 + nt*8 + (ln & 3)*2;
            float2 v0; v0.x = acc[nt][0]; v0.y = acc[nt][1];
            float2 v1; v1.x = acc[nt][2]; v1.y = acc[nt][3];
            *(float2*)&out[(size_t)b*65536 + (size_t)rr*512 + cc]     = v0;
            *(float2*)&out[(size_t)b*65536 + (size_t)(rr+8)*512 + cc] = v1;
        }
    }
}

// =====================================================================
extern "C" void kernel_launch(void* const* d_in, const int* in_sizes, int n_in,
                              void* d_out, int out_size)
{
    const float* x  = (const float*)d_in[0];
    const float* Wq = (const float*)d_in[1];
    const float* Wk = (const float*)d_in[2];
    const float* Wv = (const float*)d_in[3];
    const float* Wo = (const float*)d_in[4];
    float* out = (float*)d_out;

    cudaFuncSetAttribute(k_all, cudaFuncAttributeMaxDynamicSharedMemorySize, SMEM_ALL);
    k_all<<<NPREP + NQKV + NATTN + NOUT, 256, SMEM_ALL>>>(x, Wq, Wk, Wv, Wo, out);
}

// round 17
// speedup vs baseline: 1.0661x; 1.0661x over previous
#include <cuda_runtime.h>
#include <cuda_fp16.h>
#include <cstdint>

#define BB 24
#define DM 128
#define HH 8
#define DK 16
#define LL 512
#define HB (HH*BB)   // 192

// fp16 hi/lo intermediates + dependency counters (allocation-free)
__device__ __half gXh[BB*DM*LL], gXl[BB*DM*LL];
__device__ __half gQh[HB*DK*LL], gQl[HB*DK*LL];
__device__ __half gKh[HB*DK*LL], gKl[HB*DK*LL];
__device__ __half gVh[HB*DK*LL];
__device__ __half gHh[BB*DM*LL], gHl[BB*DM*LL];
__device__ int c_prep[BB];
__device__ int c_attn[BB];

// ---- mma/ldmatrix helpers ----
__device__ __forceinline__ uint32_t smem_u32(const void* p) {
    uint32_t a;
    asm("{ .reg .u64 t; cvta.to.shared.u64 t, %1; cvt.u32.u64 %0, t; }" : "=r"(a) : "l"(p));
    return a;
}
__device__ __forceinline__ void ldsm4(uint32_t* r, uint32_t a) {
    asm volatile("ldmatrix.sync.aligned.m8n8.x4.shared.b16 {%0,%1,%2,%3}, [%4];"
        : "=r"(r[0]), "=r"(r[1]), "=r"(r[2]), "=r"(r[3]) : "r"(a));
}
__device__ __forceinline__ void ldsm4t(uint32_t* r, uint32_t a) {
    asm volatile("ldmatrix.sync.aligned.m8n8.x4.trans.shared.b16 {%0,%1,%2,%3}, [%4];"
        : "=r"(r[0]), "=r"(r[1]), "=r"(r[2]), "=r"(r[3]) : "r"(a));
}
__device__ __forceinline__ void mma_f16(float* d, const uint32_t* a, const uint32_t* b) {
    asm volatile("mma.sync.aligned.m16n8k16.row.col.f32.f16.f16.f32 "
        "{%0,%1,%2,%3}, {%4,%5,%6,%7}, {%8,%9}, {%0,%1,%2,%3};"
        : "+f"(d[0]), "+f"(d[1]), "+f"(d[2]), "+f"(d[3])
        : "r"(a[0]), "r"(a[1]), "r"(a[2]), "r"(a[3]), "r"(b[0]), "r"(b[1]));
}
__device__ __forceinline__ float ex2f(float x) {
    float r; asm("ex2.approx.f32 %0, %1;" : "=f"(r) : "f"(x)); return r;
}
__device__ __forceinline__ uint32_t cvt_f16x2(float hi, float lo) {
    uint32_t r; asm("cvt.rn.f16x2.f32 %0, %1, %2;" : "=r"(r) : "f"(hi), "f"(lo)); return r;
}
__device__ __forceinline__ uint32_t ex2_f16x2(uint32_t x) {
    uint32_t r; asm("ex2.approx.f16x2 %0, %1;" : "=r"(r) : "r"(x)); return r;
}
__device__ __forceinline__ void packhl(float p0, float p1, uint32_t& h, uint32_t& l) {
    __half2 hh = __floats2half2_rn(p0, p1);
    float2 f = __half22float2(hh);
    __half2 ll = __floats2half2_rn(p0 - f.x, p1 - f.y);
    h = *(uint32_t*)&hh; l = *(uint32_t*)&ll;
}
__device__ __forceinline__ uint32_t packh(float p0, float p1) {
    __half2 hh = __floats2half2_rn(p0, p1);
    return *(uint32_t*)&hh;
}
__device__ __forceinline__ void split1(float v, __half& h, __half& l) {
    h = __float2half_rn(v);
    l = __float2half_rn(v - __half2float(h));
}
__device__ __forceinline__ void spin_until(volatile int* c, int target) {
    while (*c < target) __nanosleep(64);
}

// =====================================================================
// K1: prep (96 CTAs) + QKV projection (384 CTAs). 512 thr, 95.7KB.
// V computed 1-term (W_h * x_h): V is stored fp16-only downstream.
// =====================================================================
#define QW_H 0          // 48*136*2 = 13056
#define QW_L 13056
#define QX_H 26112      // 128*136*2 = 34816
#define QX_L 60928
#define Q_SMEM 95744
#define NPREP 96

__global__ void __launch_bounds__(512, 2) k_main1(const float* __restrict__ x,
                                                  const float* __restrict__ Wq,
                                                  const float* __restrict__ Wk,
                                                  const float* __restrict__ Wv)
{
    const int bid = blockIdx.x, t = threadIdx.x;

    // ---------------- prep CTAs: x -> fp16 hi/lo ----------------
    if (bid < NPREP) {
        if (bid == 0 && t == 0) {
            #pragma unroll
            for (int i = 0; i < BB; ++i) c_attn[i] = 0;   // reset K2 counters
        }
        const int b = bid >> 2;
        const size_t base = (size_t)bid * 4096;           // float4 units
        #pragma unroll
        for (int j = 0; j < 8; ++j) {
            size_t i = base + t + (size_t)j * 512;
            float4 v = *(const float4*)(x + i * 4);
            uint32_t h0,l0,h1,l1;
            packhl(v.x, v.y, h0, l0); packhl(v.z, v.w, h1, l1);
            uint2 uh; uh.x = h0; uh.y = h1;
            uint2 ul; ul.x = l0; ul.y = l1;
            *(uint2*)&gXh[i * 4] = uh;
            *(uint2*)&gXl[i * 4] = ul;
        }
        __threadfence();
        __syncthreads();
        if (t == 0) atomicAdd(&c_prep[b], 1);
        return;
    }

    // ---------------- qkv CTAs ----------------
    extern __shared__ char smc[];
    const uint32_t su = smem_u32(smc);
    __half* sWh = (__half*)(smc + QW_H);
    __half* sWl = (__half*)(smc + QW_L);
    const int t2 = t, w = t2 >> 5, ln = t2 & 31;
    const int qb = bid - NPREP;
    const int hb = qb >> 1, half = qb & 1;
    const int b = hb % BB;
    const int lw = w & 7, mg = w >> 3;
    const int nmt = mg ? 1 : 2;
    const int rsel = ln & 15;
    const uint32_t csel = (uint32_t)(ln >> 4) * 16;
    const int trow = (ln & 7) + ((ln >> 4) << 3);
    const uint32_t tcb = (uint32_t)((ln >> 3) & 1) * 16;

    for (int i4 = t; i4 < 1536; i4 += 512) {
        int r = i4 >> 5, c4 = i4 & 31;
        const float* src = (r < 16) ? (Wq + (size_t)hb*2048 + r*128)
                         : (r < 32) ? (Wk + (size_t)hb*2048 + (r-16)*128)
                                    : (Wv + (size_t)hb*2048 + (r-32)*128);
        float4 v = *(const float4*)(src + c4*4);
        uint32_t h0,l0,h1,l1;
        packhl(v.x, v.y, h0, l0); packhl(v.z, v.w, h1, l1);
        uint2 uh; uh.x = h0; uh.y = h1;
        uint2 ul; ul.x = l0; ul.y = l1;
        *(uint2*)&sWh[r*136 + c4*4] = uh;
        *(uint2*)&sWl[r*136 + c4*4] = ul;
    }

    if (t == 0) { spin_until(c_prep + b, 4); __threadfence(); }

    for (int lt = half*2; lt < half*2 + 2; ++lt) {
        __syncthreads();
        for (int i4 = t; i4 < 2048; i4 += 512) {
            int d = i4 >> 4, j = i4 & 15;
            uint32_t dofs = (uint32_t)(d*272 + j*16);
            size_t gofs = (size_t)b*65536 + (size_t)d*512 + lt*128 + j*8;
            *(uint4*)(smc + QX_H + dofs) = *(const uint4*)(gXh + gofs);
            *(uint4*)(smc + QX_L + dofs) = *(const uint4*)(gXl + gofs);
        }
        __syncthreads();

        float acc[2][2][4];
        #pragma unroll
        for (int mt = 0; mt < 2; ++mt)
            #pragma unroll
            for (int nt = 0; nt < 2; ++nt)
                #pragma unroll
                for (int r = 0; r < 4; ++r) acc[mt][nt][r] = 0.f;

        #pragma unroll
        for (int kt = 0; kt < 8; ++kt) {
            uint32_t bh[2][2], r4[4];
            uint32_t ad = su + QX_H + (uint32_t)((kt*16 + trow)*272) + (uint32_t)(lw*16)*2 + tcb;
            ldsm4t(r4, ad);
            bh[0][0]=r4[0]; bh[0][1]=r4[2]; bh[1][0]=r4[1]; bh[1][1]=r4[3];
            if (mg == 0) {
                // Q,K tiles: 3-term split
                uint32_t bl[2][2];
                ldsm4t(r4, ad + (QX_L - QX_H));
                bl[0][0]=r4[0]; bl[0][1]=r4[2]; bl[1][0]=r4[1]; bl[1][1]=r4[3];
                #pragma unroll
                for (int mt = 0; mt < 2; ++mt) {
                    uint32_t ah[4], al[4];
                    uint32_t aad = su + QW_H + (uint32_t)((mt*16 + rsel)*272) + csel + kt*32;
                    ldsm4(ah, aad);
                    ldsm4(al, aad + (QW_L - QW_H));
                    #pragma unroll
                    for (int nt = 0; nt < 2; ++nt) {
                        mma_f16(acc[mt][nt], ah, bh[nt]);
                        mma_f16(acc[mt][nt], ah, bl[nt]);
                        mma_f16(acc[mt][nt], al, bh[nt]);
                    }
                }
            } else {
                // V tile: 1-term (fp16 output precision anyway)
                uint32_t ah[4];
                uint32_t aad = su + QW_H + (uint32_t)((2*16 + rsel)*272) + csel + kt*32;
                ldsm4(ah, aad);
                #pragma unroll
                for (int nt = 0; nt < 2; ++nt)
                    mma_f16(acc[0][nt], ah, bh[nt]);
            }
        }

        #pragma unroll
        for (int mt = 0; mt < 2; ++mt) {
            if (mt >= nmt) break;
            #pragma unroll
            for (int nt = 0; nt < 2; ++nt) {
                int rr = ln >> 2;
                int cc = lt*128 + lw*16 + nt*8 + (ln & 3)*2;
                size_t o0 = (size_t)hb*8192 + (size_t)rr*512 + cc;
                size_t o1 = (size_t)hb*8192 + (size_t)(rr+8)*512 + cc;
                if (mg) {
                    *(uint32_t*)&gVh[o0] = packh(acc[mt][nt][0], acc[mt][nt][1]);
                    *(uint32_t*)&gVh[o1] = packh(acc[mt][nt][2], acc[mt][nt][3]);
                } else {
                    __half* dh = mt ? gKh : gQh;
                    __half* dl = mt ? gKl : gQl;
                    uint32_t h0,l0,h1,l1;
                    packhl(acc[mt][nt][0], acc[mt][nt][1], h0, l0);
                    packhl(acc[mt][nt][2], acc[mt][nt][3], h1, l1);
                    *(uint32_t*)&dh[o0] = h0; *(uint32_t*)&dl[o0] = l0;
                    *(uint32_t*)&dh[o1] = h1; *(uint32_t*)&dl[o1] = l1;
                }
            }
        }
    }
}

// =====================================================================
// K2: attention (768 CTAs) + output GEMM (768 CTAs). 256 thr, 58.6KB.
// (unchanged from R15 pass)
// =====================================================================
#define A_QH 0          // 16*520*2 = 16640
#define A_QL 16640
#define A_VH 33280
#define A_KH 49920      // 16*136*2 = 4352
#define A_KL 54272
#define A_SMEM 58624
#define OW_H 0          // 32*136*2 = 8704
#define OW_L 8704
#define OX_H 17408      // 128*144 = 18432
#define OX_L 35840      // total 54272

__global__ void __launch_bounds__(256, 3) k_main2(const float* __restrict__ Wo,
                                                  float* __restrict__ out)
{
    extern __shared__ char smc[];
    const uint32_t su = smem_u32(smc);
    const int bid = blockIdx.x, t = threadIdx.x;
    const int w = t >> 5, ln = t & 31;
    const int rsel = ln & 15;
    const uint32_t csel = (uint32_t)(ln >> 4) * 16;
    const int trow = (ln & 7) + ((ln >> 4) << 3);
    const uint32_t tcb = (uint32_t)((ln >> 3) & 1) * 16;

    if (bid < 768) {
        // ---------------- attention ----------------
        if (bid == 0 && t == 0) {
            #pragma unroll
            for (int i = 0; i < BB; ++i) c_prep[i] = 0;   // reset K1 counters
        }
        const int hb = bid >> 2, ms = bid & 3;
        const int b = hb % BB, h = hb / BB;
        const int m0 = ms * 128;

        {
            const __half* s0 = gQh + (size_t)hb*8192;
            const __half* s1 = gQl + (size_t)hb*8192;
            const __half* s2 = gVh + (size_t)hb*8192;
            for (int j = t; j < 1024; j += 256) {
                int k = j >> 6, c = j & 63;
                uint32_t dofs = (uint32_t)(k*1040 + c*16);
                *(uint4*)(smc + A_QH + dofs) = *(const uint4*)(s0 + k*512 + c*8);
                *(uint4*)(smc + A_QL + dofs) = *(const uint4*)(s1 + k*512 + c*8);
                *(uint4*)(smc + A_VH + dofs) = *(const uint4*)(s2 + k*512 + c*8);
            }
            for (int j = t; j < 256; j += 256) {
                int k = j >> 4, c = j & 15;
                uint32_t dofs = (uint32_t)(k*272 + c*16);
                *(uint4*)(smc + A_KH + dofs) = *(const uint4*)(gKh + (size_t)hb*8192 + k*512 + m0 + c*8);
                *(uint4*)(smc + A_KL + dofs) = *(const uint4*)(gKl + (size_t)hb*8192 + k*512 + m0 + c*8);
            }
        }
        __syncthreads();

        uint32_t kh[4], kl[4];
        {
            uint32_t ad = su + A_KH + (uint32_t)(trow*272) + (uint32_t)(w*16)*2 + tcb;
            ldsm4t(kh, ad);
            ldsm4t(kl, ad + (A_KL - A_KH));
        }

        uint32_t bones[2];
        bones[0] = (ln < 4) ? 0x3C003C00u : 0u;
        bones[1] = bones[0];

        float mx[2] = {-1e30f, -1e30f}, O[2][4], Od[4];
        #pragma unroll
        for (int vt = 0; vt < 2; ++vt)
            #pragma unroll
            for (int r = 0; r < 4; ++r) O[vt][r] = 0.f;
        #pragma unroll
        for (int r = 0; r < 4; ++r) Od[r] = 0.f;

        const float C = 0.36067376022224085f;   // 0.25 * log2(e)

        for (int c = 0; c < 16; ++c) {
            uint32_t vb[2][2][2];
            #pragma unroll
            for (int st = 0; st < 2; ++st) {
                uint32_t r4[4];
                uint32_t ad = su + A_VH + (uint32_t)(rsel * 1040 + (c*32 + st*16) * 2) + csel;
                ldsm4(r4, ad);
                vb[st][0][0]=r4[0]; vb[st][0][1]=r4[2]; vb[st][1][0]=r4[1]; vb[st][1][1]=r4[3];
            }
            uint32_t qh[4][2], ql[4][2];
            #pragma unroll
            for (int q = 0; q < 2; ++q) {
                uint32_t r4[4];
                uint32_t ad = su + A_QH + (uint32_t)(trow*1040) + (uint32_t)((c*32 + q*16)*2) + tcb;
                ldsm4t(r4, ad);
                qh[2*q][0]=r4[0]; qh[2*q][1]=r4[2]; qh[2*q+1][0]=r4[1]; qh[2*q+1][1]=r4[3];
                ldsm4t(r4, ad + (A_QL - A_QH));
                ql[2*q][0]=r4[0]; ql[2*q][1]=r4[2]; ql[2*q+1][0]=r4[1]; ql[2*q+1][1]=r4[3];
            }

            float s[4][4];
            #pragma unroll
            for (int nt = 0; nt < 4; ++nt) {
                #pragma unroll
                for (int r = 0; r < 4; ++r) s[nt][r] = 0.f;
                mma_f16(s[nt], kh, qh[nt]);
                mma_f16(s[nt], kl, qh[nt]);
                mma_f16(s[nt], kh, ql[nt]);
            }

            float cA = -1e30f, cB = -1e30f;
            #pragma unroll
            for (int nt = 0; nt < 4; ++nt) {
                cA = fmaxf(cA, fmaxf(s[nt][0], s[nt][1]));
                cB = fmaxf(cB, fmaxf(s[nt][2], s[nt][3]));
            }
            cA = fmaxf(cA, __shfl_xor_sync(0xffffffffu, cA, 1));
            cA = fmaxf(cA, __shfl_xor_sync(0xffffffffu, cA, 2));
            cB = fmaxf(cB, __shfl_xor_sync(0xffffffffu, cB, 1));
            cB = fmaxf(cB, __shfl_xor_sync(0xffffffffu, cB, 2));
            float mA = fmaxf(mx[0], cA), mB = fmaxf(mx[1], cB);
            float sA = ex2f((mx[0] - mA) * C), sB = ex2f((mx[1] - mB) * C);
            mx[0] = mA; mx[1] = mB;
            #pragma unroll
            for (int vt = 0; vt < 2; ++vt) {
                O[vt][0] *= sA; O[vt][1] *= sA;
                O[vt][2] *= sB; O[vt][3] *= sB;
            }
            Od[0] *= sA; Od[2] *= sB;

            const float nmA = -mA * C, nmB = -mB * C;
            uint32_t ph[4][2];
            #pragma unroll
            for (int nt = 0; nt < 4; ++nt) {
                float x0 = fmaf(s[nt][0], C, nmA);
                float x1 = fmaf(s[nt][1], C, nmA);
                float x2 = fmaf(s[nt][2], C, nmB);
                float x3 = fmaf(s[nt][3], C, nmB);
                ph[nt][0] = ex2_f16x2(cvt_f16x2(x1, x0));
                ph[nt][1] = ex2_f16x2(cvt_f16x2(x3, x2));
            }

            #pragma unroll
            for (int st = 0; st < 2; ++st) {
                uint32_t ah[4];
                ah[0] = ph[2*st][0];
                ah[1] = ph[2*st][1];
                ah[2] = ph[2*st+1][0];
                ah[3] = ph[2*st+1][1];
                #pragma unroll
                for (int vt = 0; vt < 2; ++vt)
                    mma_f16(O[vt], ah, vb[st][vt]);
                mma_f16(Od, ah, bones);
            }
        }

        float dnA = __shfl_sync(0xffffffffu, Od[0], ln & 28);
        float dnB = __shfl_sync(0xffffffffu, Od[2], ln & 28);
        float inv[2];
        inv[0] = 1.0f / dnA;
        inv[1] = 1.0f / dnB;

        __half* dh = gHh + ((size_t)b * DM + h * DK) * LL;
        __half* dl = gHl + ((size_t)b * DM + h * DK) * LL;
        #pragma unroll
        for (int vt = 0; vt < 2; ++vt)
            #pragma unroll
            for (int r = 0; r < 4; ++r) {
                int m = m0 + w*16 + (ln >> 2) + ((r >> 1) & 1) * 8;
                int v = vt*8 + (ln & 3)*2 + (r & 1);
                float val = O[vt][r] * inv[(r >> 1) & 1];
                __half hi, lo; split1(val, hi, lo);
                dh[(size_t)v * LL + m] = hi;
                dl[(size_t)v * LL + m] = lo;
            }
        __threadfence();
        __syncthreads();
        if (t == 0) atomicAdd(&c_attn[b], 1);
        return;
    }

    // ---------------- output GEMM ----------------
    {
        const int obid = bid - 768;
        const int lt = obid & 7, mh = (obid >> 3) & 3, b = obid >> 5;
        __half* sWh = (__half*)(smc + OW_H);
        __half* sWl = (__half*)(smc + OW_L);
        const int lg = w & 3, mg = w >> 2;

        for (int i4 = t; i4 < 1024; i4 += 256) {
            int r = i4 >> 5, c4 = i4 & 31;
            float4 v = *(const float4*)(Wo + (size_t)b*16384 + (size_t)(mh*32 + r)*128 + c4*4);
            uint32_t h0,l0,h1,l1;
            packhl(v.x, v.y, h0, l0); packhl(v.z, v.w, h1, l1);
            uint2 uh; uh.x = h0; uh.y = h1;
            uint2 ul; ul.x = l0; ul.y = l1;
            *(uint2*)&sWh[r*136 + c4*4] = uh;
            *(uint2*)&sWl[r*136 + c4*4] = ul;
        }

        if (t == 0) { spin_until(c_attn + b, 32); __threadfence(); }
        __syncthreads();

        for (int i4 = t; i4 < 1024; i4 += 256) {
            int d = i4 >> 3, j = i4 & 7;
            uint32_t dofs = (uint32_t)(d*144 + j*16);
            size_t gofs = (size_t)b*65536 + (size_t)d*512 + lt*64 + j*8;
            *(uint4*)(smc + OX_H + dofs) = *(const uint4*)(gHh + gofs);
            *(uint4*)(smc + OX_L + dofs) = *(const uint4*)(gHl + gofs);
        }
        __syncthreads();

        float acc[2][4];
        #pragma unroll
        for (int nt = 0; nt < 2; ++nt)
            #pragma unroll
            for (int r = 0; r < 4; ++r) acc[nt][r] = 0.f;

        #pragma unroll
        for (int kt = 0; kt < 8; ++kt) {
            uint32_t bh[2][2], bl[2][2], r4[4];
            uint32_t ad = su + OX_H + (uint32_t)((kt*16 + trow)*144) + (uint32_t)(lg*16)*2 + tcb;
            ldsm4t(r4, ad);
            bh[0][0]=r4[0]; bh[0][1]=r4[2]; bh[1][0]=r4[1]; bh[1][1]=r4[3];
            ldsm4t(r4, ad + (OX_L - OX_H));
            bl[0][0]=r4[0]; bl[0][1]=r4[2]; bl[1][0]=r4[1]; bl[1][1]=r4[3];
            uint32_t ah[4], al[4];
            uint32_t aad = su + OW_H + (uint32_t)((mg*16 + rsel)*272) + csel + kt*32;
            ldsm4(ah, aad);
            ldsm4(al, aad + (OW_L - OW_H));
            #pragma unroll
            for (int nt = 0; nt < 2; ++nt) {
                mma_f16(acc[nt], ah, bh[nt]);
                mma_f16(acc[nt], ah, bl[nt]);
                mma_f16(acc[nt], al, bh[nt]);
            }
        }

        #pragma unroll
        for (int nt = 0; nt < 2; ++nt) {
            int rr = mh*32 + mg*16 + (ln >> 2);
            int cc = lt*64 + lg*16 + nt*8 + (ln & 3)*2;
            float2 v0; v0.x = acc[nt][0]; v0.y = acc[nt][1];
            float2 v1; v1.x = acc[nt][2]; v1.y = acc[nt][3];
            *(float2*)&out[(size_t)b*65536 + (size_t)rr*512 + cc]     = v0;
            *(float2*)&out[(size_t)b*65536 + (size_t)(rr+8)*512 + cc] = v1;
        }
    }
}

// =====================================================================
extern "C" void kernel_launch(void* const* d_in, const int* in_sizes, int n_in,
                              void* d_out, int out_size)
{
    const float* x  = (const float*)d_in[0];
    const float* Wq = (const float*)d_in[1];
    const float* Wk = (const float*)d_in[2];
    const float* Wv = (const float*)d_in[3];
    const float* Wo = (const float*)d_in[4];
    float* out = (float*)d_out;

    cudaFuncSetAttribute(k_main1, cudaFuncAttributeMaxDynamicSharedMemorySize, Q_SMEM);
    cudaFuncSetAttribute(k_main2, cudaFuncAttributeMaxDynamicSharedMemorySize, A_SMEM);

    k_main1<<<NPREP + HB * 2, 512, Q_SMEM>>>(x, Wq, Wk, Wv);
    k_main2<<<768 + 768, 256, A_SMEM>>>(Wo, out);
}